// round 8
// baseline (speedup 1.0000x reference)
#include <cuda_runtime.h>
#include <cuda_fp16.h>
#include <math.h>
#include <stdint.h>

// ---------------------------------------------------------------------------
// REGC hetero-GNN. Types [author 200000, fos 30000, inst 5000, paper 150000].
// 7 relations x 400000 edges. L1: 128->256 (H=8,NB=4,DH=32) mean+max.
// L2: 256->349 mean. cp.async-pipelined fp16 HMMA GEMMs with packed weights;
// CSR aggregation (no feature atomics); fp16 intermediates.
// ---------------------------------------------------------------------------

#define E     400000
#define RTOT  885000
#define TOTE  2800000
#define NPAD  384

__device__ __half g_xh   [(size_t)385000 * 128];   // fp16 node features
__device__ __half g_bases[(size_t)385000 * 128];
__device__ __half g_out1 [(size_t)385000 * 256];   // post-ReLU
__device__ __half g_wroot[(size_t)385000 * 32];
__device__ __half g_wrel [(size_t)RTOT * 64];
__device__ __half g_sum2 [(size_t)RTOT * 256];
__device__ __half g_w1p  [4][(size_t)128 * NPAD];  // packed L1 weights [K][NPAD]
__device__ float  g_b1p  [4][NPAD];
__device__ __half g_w2p  [4][(size_t)1024 * NPAD]; // packed L2 weights [Kseg][NPAD]
__device__ int    g_cnt   [RTOT];
__device__ int    g_rowptr[RTOT + 1];
__device__ int    g_cursor[RTOT];
__device__ int    g_ebuf  [TOTE];
__device__ int    g_bsum  [512];

__device__ __constant__ int c_ST[7]   = {0, 2, 0, 3, 3, 3, 1};
__device__ __constant__ int c_OFF[4]  = {0, 200000, 230000, 235000};
__device__ __constant__ int c_ROFF[7] = {0, 5000, 205000, 355000, 555000, 705000, 735000};

__device__ __forceinline__ void cpa16(uint32_t dst, const void* src, int sz)
{
    asm volatile("cp.async.cg.shared.global [%0], [%1], 16, %2;"
                 :: "r"(dst), "l"(src), "r"(sz));
}

// ---------------------------------------------------------------------------
// Pipelined fp16 GEMM. A: up to 4 row-segments (fp16, aStride halves/row).
// B: packed [nit*32][NPAD] fp16. 2-stage cp.async. BM=128 BN=64 BK=32.
// mode 0: C f32 [M][349] = acc + bias  (L2)
// mode 1: scatter columns: [0,128)->g_bases, [128,160)->g_wroot,
//         [160,160+64R)->g_wrel  (L1; bias from packed b1p)
// ---------------------------------------------------------------------------
__global__ void __launch_bounds__(256) gemm_pipe(
    const __half* A0, const __half* A1, const __half* A2, const __half* A3,
    const __half* __restrict__ Bp, const float* __restrict__ bias,
    float* __restrict__ Cf,
    int M, int aStride, int segShift, int nit, int mode,
    int nodeOff, int ro0, int ro1, int ro2, int Ncols)
{
    __shared__ __align__(16) __half sm[2 * 128 * 40 + 2 * 32 * 72];

    const __half* Aseg[4] = {A0, A1, A2, A3};
    const int tid  = threadIdx.x;
    const int lane = tid & 31;
    const int warp = tid >> 5;
    const int wm = (warp & 3) * 32;
    const int wn = (warp >> 2) * 32;
    const int m0 = blockIdx.y * 128;
    const int n0 = blockIdx.x * 64;

    const uint32_t sbase = (uint32_t)__cvta_generic_to_shared(sm);
    const uint32_t asOff[2] = {sbase, sbase + 128 * 40 * 2};
    const uint32_t bsOff[2] = {sbase + 2 * 128 * 40 * 2,
                               sbase + 2 * 128 * 40 * 2 + 32 * 72 * 2};

    auto docopy = [&](int stage, int it) {
        const int seg = it >> segShift;
        const int k0 = (it - (seg << segShift)) * 32;
        const __half* Ab = Aseg[seg];
        const uint32_t as = asOff[stage];
        const uint32_t bs = bsOff[stage];
        // A tile: 128 rows x 32 halves = 512 x 16B chunks, 2 per thread
#pragma unroll
        for (int j = 0; j < 2; j++) {
            const int q = tid * 2 + j;
            const int row = q >> 2, kc = (q & 3) * 8;
            const int gm = m0 + row;
            const int valid = gm < M;
            const __half* src = Ab + (size_t)(valid ? gm : 0) * aStride + k0 + kc;
            cpa16(as + (row * 40 + kc) * 2, src, valid ? 16 : 0);
        }
        // B tile: 32 rows x 64 halves = 256 x 16B chunks, 1 per thread (all 256)
        {
            const int krow = tid >> 3, nc = (tid & 7) * 8;
            const __half* src = Bp + (size_t)(it * 32 + krow) * NPAD + n0 + nc;
            cpa16(bs + (krow * 72 + nc) * 2, src, 16);
        }
        asm volatile("cp.async.commit_group;");
    };

    float acc[2][4][4];
#pragma unroll
    for (int mi = 0; mi < 2; mi++)
#pragma unroll
        for (int nj = 0; nj < 4; nj++)
#pragma unroll
            for (int r = 0; r < 4; r++) acc[mi][nj][r] = 0.f;

    auto compute = [&](int stage) {
        const uint32_t aAddr0 = asOff[stage] +
            (uint32_t)((wm + (lane & 15)) * 80 + ((lane >> 4) * 8) * 2);
        const uint32_t bAddr0 = bsOff[stage] +
            (uint32_t)(((lane & 15)) * 144 + (wn + (lane >> 4) * 8) * 2);
#pragma unroll
        for (int kk = 0; kk < 2; kk++) {
            uint32_t a[2][4], b[4][2];
#pragma unroll
            for (int mi = 0; mi < 2; mi++) {
                uint32_t addr = aAddr0 + (uint32_t)(mi * 16 * 80 + kk * 16 * 2);
                asm volatile("ldmatrix.sync.aligned.m8n8.x4.shared.b16 {%0,%1,%2,%3}, [%4];"
                             : "=r"(a[mi][0]), "=r"(a[mi][1]), "=r"(a[mi][2]), "=r"(a[mi][3])
                             : "r"(addr));
            }
#pragma unroll
            for (int njp = 0; njp < 2; njp++) {
                uint32_t addr = bAddr0 + (uint32_t)(kk * 16 * 144 + njp * 16 * 2);
                asm volatile("ldmatrix.sync.aligned.m8n8.x4.trans.shared.b16 {%0,%1,%2,%3}, [%4];"
                             : "=r"(b[njp * 2][0]), "=r"(b[njp * 2][1]),
                               "=r"(b[njp * 2 + 1][0]), "=r"(b[njp * 2 + 1][1])
                             : "r"(addr));
            }
#pragma unroll
            for (int mi = 0; mi < 2; mi++)
#pragma unroll
                for (int nj = 0; nj < 4; nj++) {
                    asm volatile(
                        "mma.sync.aligned.m16n8k16.row.col.f32.f16.f16.f32 "
                        "{%0,%1,%2,%3}, {%4,%5,%6,%7}, {%8,%9}, {%0,%1,%2,%3};"
                        : "+f"(acc[mi][nj][0]), "+f"(acc[mi][nj][1]),
                          "+f"(acc[mi][nj][2]), "+f"(acc[mi][nj][3])
                        : "r"(a[mi][0]), "r"(a[mi][1]), "r"(a[mi][2]), "r"(a[mi][3]),
                          "r"(b[nj][0]), "r"(b[nj][1]));
                }
        }
    };

    docopy(0, 0);
    int buf = 0;
    for (int it = 0; it < nit; it++) {
        const bool more = (it + 1 < nit);
        if (more) docopy(buf ^ 1, it + 1);
        if (more) asm volatile("cp.async.wait_group 1;" ::: "memory");
        else      asm volatile("cp.async.wait_group 0;" ::: "memory");
        __syncthreads();
        compute(buf);
        __syncthreads();
        buf ^= 1;
    }

    // ---- epilogue ----
#pragma unroll
    for (int mi = 0; mi < 2; mi++)
#pragma unroll
        for (int nj = 0; nj < 4; nj++)
#pragma unroll
            for (int r = 0; r < 4; r++) {
                const int rp = r >> 1, cp = r & 1;
                const int row = m0 + wm + mi * 16 + (lane >> 2) + rp * 8;
                const int col = n0 + wn + nj * 8 + (lane & 3) * 2 + cp;
                if (row >= M || col >= Ncols) continue;
                const float v = acc[mi][nj][r] + bias[col];
                if (mode == 0) {
                    Cf[(size_t)row * 349 + col] = v;
                } else {
                    const __half h = __float2half_rn(v);
                    if (col < 128) {
                        g_bases[(size_t)(nodeOff + row) * 128 + col] = h;
                    } else if (col < 160) {
                        g_wroot[(size_t)(nodeOff + row) * 32 + (col - 128)] = h;
                    } else {
                        const int cc = col - 160;
                        const int rr = cc >> 6;
                        const int ro = (rr == 0) ? ro0 : ((rr == 1) ? ro1 : ro2);
                        g_wrel[(size_t)(ro + row) * 64 + (cc & 63)] = h;
                    }
                }
            }
}

// ---------------------------------------------------------------------------
// prep kernels
// ---------------------------------------------------------------------------
__global__ void cvt_half(const float* __restrict__ x, __half* __restrict__ y, int n)
{
    const int i = blockIdx.x * blockDim.x + threadIdx.x;
    if (i < n) y[i] = __float2half_rn(x[i]);
}

__global__ void pack_w1(const float* __restrict__ bases_w1,
                        const float* __restrict__ root_w1,
                        const float* __restrict__ rel_w1,
                        const float* __restrict__ root_b1,
                        const float* __restrict__ rel_b1,
                        __half* __restrict__ w1p, float* __restrict__ b1p,
                        int t, int R, int e0, int e1, int e2)
{
    const int i = blockIdx.x * blockDim.x + threadIdx.x;
    if (i >= 128 * NPAD) return;
    const int k = i / NPAD, n = i % NPAD;
    float v = 0.f, b = 0.f;
    if (n < 128) {
        v = bases_w1[k * 128 + n];
    } else if (n < 160) {
        v = root_w1[((size_t)t * 32 + (n - 128)) * 128 + k];
        b = root_b1[t * 32 + (n - 128)];
    } else {
        const int cc = n - 160;
        const int r = cc >> 6;
        if (r < R) {
            const int e = (r == 0) ? e0 : ((r == 1) ? e1 : e2);
            v = rel_w1[((size_t)e * 64 + (cc & 63)) * 128 + k];
            b = rel_b1[e * 64 + (cc & 63)];
        }
    }
    w1p[(size_t)k * NPAD + n] = __float2half_rn(v);
    if (k == 0) b1p[n] = b;
}

__global__ void pack_w2(const float* __restrict__ root_w2,
                        const float* __restrict__ rel_w2,
                        __half* __restrict__ w2p,
                        int t, int nseg, int e1, int e2, int e3)
{
    const int i = blockIdx.x * blockDim.x + threadIdx.x;
    if (i >= nseg * 256 * NPAD) return;
    const int kg = i / NPAD, n = i % NPAD;
    const int seg = kg >> 8, k = kg & 255;
    float v = 0.f;
    if (n < 349) {
        if (seg == 0) v = root_w2[((size_t)t * 349 + n) * 256 + k];
        else {
            const int e = (seg == 1) ? e1 : ((seg == 2) ? e2 : e3);
            v = rel_w2[((size_t)e * 349 + n) * 256 + k];
        }
    }
    w2p[(size_t)kg * NPAD + n] = __float2half_rn(v);
}

// ---------------------------------------------------------------------------
// CSR build (validated R5/R6)
// ---------------------------------------------------------------------------
__global__ void count_kernel(const int* __restrict__ dst_idx)
{
    const int e = blockIdx.y;
    const int i = blockIdx.x * blockDim.x + threadIdx.x;
    if (i >= E) return;
    atomicAdd(&g_cnt[c_ROFF[e] + dst_idx[(size_t)e * E + i]], 1);
}

__global__ void __launch_bounds__(256) scan1_kernel()
{
    __shared__ int s[256];
    const int tid = threadIdx.x;
    const int tbase = blockIdx.x * 2048 + tid * 8;
    int vals[8];
    int tsum = 0;
#pragma unroll
    for (int j = 0; j < 8; j++) {
        int v = (tbase + j < RTOT) ? g_cnt[tbase + j] : 0;
        vals[j] = tsum;
        tsum += v;
    }
    s[tid] = tsum;
    __syncthreads();
    for (int off = 1; off < 256; off <<= 1) {
        int t = (tid >= off) ? s[tid - off] : 0;
        __syncthreads();
        s[tid] += t;
        __syncthreads();
    }
    const int texcl = (tid > 0) ? s[tid - 1] : 0;
    if (tid == 255) g_bsum[blockIdx.x] = s[255];
#pragma unroll
    for (int j = 0; j < 8; j++)
        if (tbase + j < RTOT) g_rowptr[tbase + j] = vals[j] + texcl;
}

__global__ void __launch_bounds__(512) scan2_kernel(int nb)
{
    __shared__ int s[512];
    const int tid = threadIdx.x;
    s[tid] = (tid < nb) ? g_bsum[tid] : 0;
    __syncthreads();
    for (int off = 1; off < 512; off <<= 1) {
        int t = (tid >= off) ? s[tid - off] : 0;
        __syncthreads();
        s[tid] += t;
        __syncthreads();
    }
    g_bsum[tid] = (tid > 0) ? s[tid - 1] : 0;
}

__global__ void scan3_kernel()
{
    const int i = blockIdx.x * blockDim.x + threadIdx.x;
    if (i < RTOT) {
        int v = g_rowptr[i] + g_bsum[i >> 11];
        g_rowptr[i] = v;
        g_cursor[i] = v;
    } else if (i == RTOT) {
        g_rowptr[RTOT] = TOTE;
    }
}

__global__ void fill_kernel(const int* __restrict__ src_idx,
                            const int* __restrict__ dst_idx)
{
    const int e = blockIdx.y;
    const int i = blockIdx.x * blockDim.x + threadIdx.x;
    if (i >= E) return;
    const int d = dst_idx[(size_t)e * E + i];
    const int s = src_idx[(size_t)e * E + i];
    const int pos = atomicAdd(&g_cursor[c_ROFF[e] + d], 1);
    g_ebuf[pos] = c_OFF[c_ST[e]] + s;
}

// ---------------------------------------------------------------------------
// L1 fused aggregate+combine (validated R6)
// ---------------------------------------------------------------------------
__global__ void __launch_bounds__(256) l1_fused_kernel(
    __half* __restrict__ out1, const __half* __restrict__ wroot,
    int tOff, int Nn, int roff0, int roff1, int roff2, int R)
{
    __shared__ float smb[8][128];
    __shared__ float sma[8][256];

    const int warp = threadIdx.x >> 5;
    const int lane = threadIdx.x & 31;
    const int n = blockIdx.x * 8 + warp;
    if (n >= Nn) return;
    const int c4 = lane * 4;
    const int h  = lane >> 2;

    {
        const uint2 raw = *(const uint2*)(g_bases + (size_t)(tOff + n) * 128 + c4);
        const float2 lo = __half22float2(*(const __half2*)&raw.x);
        const float2 hi = __half22float2(*(const __half2*)&raw.y);
        smb[warp][c4 + 0] = lo.x; smb[warp][c4 + 1] = lo.y;
        smb[warp][c4 + 2] = hi.x; smb[warp][c4 + 3] = hi.y;
    }
    __syncwarp();

    float val[8];
    {
        const uint2 raw = *(const uint2*)(wroot + (size_t)n * 32 + h * 4);
        const float2 w01 = __half22float2(*(const __half2*)&raw.x);
        const float2 w23 = __half22float2(*(const __half2*)&raw.y);
#pragma unroll
        for (int j = 0; j < 8; j++) {
            const int dd = (lane * 8 + j) & 31;
            val[j] = w01.x * smb[warp][dd] + w01.y * smb[warp][32 + dd] +
                     w23.x * smb[warp][64 + dd] + w23.y * smb[warp][96 + dd];
        }
    }

    const int roffs[3] = {roff0, roff1, roff2};
    for (int r = 0; r < R; r++) {
        const int g = roffs[r] + n;
        const int rs = g_rowptr[g];
        const int re = g_rowptr[g + 1];
        const int ct = re - rs;
        float4 s4 = make_float4(0.f, 0.f, 0.f, 0.f);
        float4 m4 = make_float4(-INFINITY, -INFINITY, -INFINITY, -INFINITY);
        for (int k = rs; k < re; k++) {
            const uint2 raw = *(const uint2*)(g_bases + (size_t)g_ebuf[k] * 128 + c4);
            const float2 lo = __half22float2(*(const __half2*)&raw.x);
            const float2 hi = __half22float2(*(const __half2*)&raw.y);
            s4.x += lo.x; s4.y += lo.y; s4.z += hi.x; s4.w += hi.y;
            m4.x = fmaxf(m4.x, lo.x); m4.y = fmaxf(m4.y, lo.y);
            m4.z = fmaxf(m4.z, hi.x); m4.w = fmaxf(m4.w, hi.y);
        }
        const float inv = 1.f / (float)(ct > 1 ? ct : 1);
        s4.x *= inv; s4.y *= inv; s4.z *= inv; s4.w *= inv;
        if (ct == 0) m4 = make_float4(0.f, 0.f, 0.f, 0.f);
        *(float4*)&sma[warp][c4]       = s4;
        *(float4*)&sma[warp][128 + c4] = m4;
        __syncwarp();
        const uint4 raw = *(const uint4*)(g_wrel + (size_t)g * 64 + h * 8);
        const float2 w01 = __half22float2(*(const __half2*)&raw.x);
        const float2 w23 = __half22float2(*(const __half2*)&raw.y);
        const float2 w45 = __half22float2(*(const __half2*)&raw.z);
        const float2 w67 = __half22float2(*(const __half2*)&raw.w);
        const float wv[8] = {w01.x, w01.y, w23.x, w23.y, w45.x, w45.y, w67.x, w67.y};
#pragma unroll
        for (int j = 0; j < 8; j++) {
            const int dd = (lane * 8 + j) & 31;
#pragma unroll
            for (int b = 0; b < 8; b++)
                val[j] += wv[b] * sma[warp][b * 32 + dd];
        }
        __syncwarp();
    }

    union { __half2 h[4]; uint4 u; } pk;
#pragma unroll
    for (int q = 0; q < 4; q++)
        pk.h[q] = __floats2half2_rn(fmaxf(val[2 * q], 0.f), fmaxf(val[2 * q + 1], 0.f));
    *(uint4*)(out1 + (size_t)n * 256 + lane * 8) = pk.u;
}

// ---------------------------------------------------------------------------
// L2 aggregation (validated R6)
// ---------------------------------------------------------------------------
__global__ void __launch_bounds__(256) l2_agg_kernel()
{
    const int warp = threadIdx.x >> 5;
    const int lane = threadIdx.x & 31;
    const int g = blockIdx.x * 8 + warp;
    if (g >= RTOT) return;
    const int c8 = lane * 8;
    const int rs = g_rowptr[g];
    const int re = g_rowptr[g + 1];
    const int ct = re - rs;
    float a[8];
#pragma unroll
    for (int j = 0; j < 8; j++) a[j] = 0.f;
    for (int k = rs; k < re; k++) {
        const uint4 raw = *(const uint4*)(g_out1 + (size_t)g_ebuf[k] * 256 + c8);
        const float2 v0 = __half22float2(*(const __half2*)&raw.x);
        const float2 v1 = __half22float2(*(const __half2*)&raw.y);
        const float2 v2 = __half22float2(*(const __half2*)&raw.z);
        const float2 v3 = __half22float2(*(const __half2*)&raw.w);
        a[0] += v0.x; a[1] += v0.y; a[2] += v1.x; a[3] += v1.y;
        a[4] += v2.x; a[5] += v2.y; a[6] += v3.x; a[7] += v3.y;
    }
    const float inv = 1.f / (float)(ct > 1 ? ct : 1);
    union { __half2 h[4]; uint4 u; } pk;
#pragma unroll
    for (int q = 0; q < 4; q++)
        pk.h[q] = __floats2half2_rn(a[2 * q] * inv, a[2 * q + 1] * inv);
    *(uint4*)(g_sum2 + (size_t)g * 256 + c8) = pk.u;
}

// ---------------------------------------------------------------------------
// host
// ---------------------------------------------------------------------------
extern "C" void kernel_launch(void* const* d_in, const int* in_sizes, int n_in,
                              void* d_out, int out_size)
{
    const float* x_paper    = (const float*)d_in[0];
    const float* emb_author = (const float*)d_in[1];
    const float* emb_fos    = (const float*)d_in[2];
    const float* emb_inst   = (const float*)d_in[3];
    const float* bases_w1   = (const float*)d_in[4];
    const float* rel_w1     = (const float*)d_in[5];
    const float* rel_b1     = (const float*)d_in[6];
    const float* root_w1    = (const float*)d_in[7];
    const float* root_b1    = (const float*)d_in[8];
    const float* rel_w2     = (const float*)d_in[9];
    const float* root_w2    = (const float*)d_in[10];
    const float* root_b2    = (const float*)d_in[11];
    const int*   src_idx    = (const int*)d_in[12];
    const int*   dst_idx    = (const int*)d_in[13];
    float* out = (float*)d_out;

    static const int NUMSh[4] = {200000, 30000, 5000, 150000};
    static const int OFFh[4]  = {0, 200000, 230000, 235000};
    static const int DT[7] = {2, 0, 3, 0, 3, 1, 3};
    static const int ROFFh[7] = {0, 5000, 205000, 355000, 555000, 705000, 735000};

    __half *xh_p, *bases_p, *out1_p, *wroot_p, *wrel_p, *sum2_p, *w1p_p, *w2p_p;
    float* b1p_p;
    int* cnt_p;
    cudaGetSymbolAddress((void**)&xh_p,    g_xh);
    cudaGetSymbolAddress((void**)&bases_p, g_bases);
    cudaGetSymbolAddress((void**)&out1_p,  g_out1);
    cudaGetSymbolAddress((void**)&wroot_p, g_wroot);
    cudaGetSymbolAddress((void**)&wrel_p,  g_wrel);
    cudaGetSymbolAddress((void**)&sum2_p,  g_sum2);
    cudaGetSymbolAddress((void**)&w1p_p,   g_w1p);
    cudaGetSymbolAddress((void**)&b1p_p,   g_b1p);
    cudaGetSymbolAddress((void**)&w2p_p,   g_w2p);
    cudaGetSymbolAddress((void**)&cnt_p,   g_cnt);

    const float* xs[4] = {emb_author, emb_fos, emb_inst, x_paper};

    // ---- CSR build ----
    cudaMemsetAsync(cnt_p, 0, (size_t)RTOT * sizeof(int));
    {
        dim3 grid((E + 255) / 256, 7);
        count_kernel<<<grid, 256>>>(dst_idx);
    }
    scan1_kernel<<<(RTOT + 2047) / 2048, 256>>>();
    scan2_kernel<<<1, 512>>>((RTOT + 2047) / 2048);
    scan3_kernel<<<(RTOT + 1 + 255) / 256, 256>>>();
    {
        dim3 grid((E + 255) / 256, 7);
        fill_kernel<<<grid, 256>>>(src_idx, dst_idx);
    }

    // ---- prep: fp16 features + packed weights ----
    for (int t = 0; t < 4; t++) {
        const int n = NUMSh[t] * 128;
        cvt_half<<<(n + 255) / 256, 256>>>(xs[t], xh_p + (size_t)OFFh[t] * 128, n);
    }
    int relsOf[4][3], Rof[4];
    for (int t = 0; t < 4; t++) {
        Rof[t] = 0;
        for (int e = 0; e < 7; e++)
            if (DT[e] == t) relsOf[t][Rof[t]++] = e;
        for (int r = Rof[t]; r < 3; r++) relsOf[t][r] = relsOf[t][0];
    }
    for (int t = 0; t < 4; t++) {
        pack_w1<<<(128 * NPAD + 255) / 256, 256>>>(
            bases_w1, root_w1, rel_w1, root_b1, rel_b1,
            w1p_p + (size_t)t * 128 * NPAD, b1p_p + (size_t)t * NPAD,
            t, Rof[t], relsOf[t][0], relsOf[t][1], relsOf[t][2]);
        const int nseg = 1 + Rof[t];
        pack_w2<<<(nseg * 256 * NPAD + 255) / 256, 256>>>(
            root_w2, rel_w2, w2p_p + (size_t)t * 1024 * NPAD,
            t, nseg, relsOf[t][0], relsOf[t][1], relsOf[t][2]);
    }

    // ---- layer-1 merged GEMM per type (bases | wroot | wrel) ----
    for (int t = 0; t < 4; t++) {
        const int Ncols = 160 + 64 * Rof[t];
        const __half* A = xh_p + (size_t)OFFh[t] * 128;
        dim3 grid((Ncols + 63) / 64, (NUMSh[t] + 127) / 128);
        gemm_pipe<<<grid, 256>>>(
            A, A, A, A, w1p_p + (size_t)t * 128 * NPAD, b1p_p + (size_t)t * NPAD,
            out, NUMSh[t], 128, 30, 4, 1,
            OFFh[t], ROFFh[relsOf[t][0]], ROFFh[relsOf[t][1]], ROFFh[relsOf[t][2]],
            Ncols);
    }

    // ---- layer-1 fused aggregate+combine ----
    for (int t = 0; t < 4; t++) {
        l1_fused_kernel<<<(NUMSh[t] + 7) / 8, 256>>>(
            out1_p + (size_t)OFFh[t] * 256, wroot_p + (size_t)OFFh[t] * 32,
            OFFh[t], NUMSh[t],
            ROFFh[relsOf[t][0]], ROFFh[relsOf[t][1]], ROFFh[relsOf[t][2]], Rof[t]);
    }

    // ---- layer-2 aggregation ----
    l2_agg_kernel<<<(RTOT + 7) / 8, 256>>>();

    // ---- layer-2 multi-segment GEMM per type ----
    for (int t = 0; t < 4; t++) {
        const __half* A[4];
        A[0] = out1_p + (size_t)OFFh[t] * 256;
        int nseg = 1;
        for (int r = 0; r < Rof[t]; r++)
            A[nseg++] = sum2_p + (size_t)ROFFh[relsOf[t][r]] * 256;
        for (int s2 = nseg; s2 < 4; s2++) A[s2] = A[0];
        dim3 grid(6, (NUMSh[t] + 127) / 128);
        gemm_pipe<<<grid, 256>>>(
            A[0], A[1], A[2], A[3], w2p_p + (size_t)t * 1024 * NPAD,
            root_b2 + (size_t)t * 349,
            out + (size_t)OFFh[t] * 349, NUMSh[t], 256, 3, nseg * 8, 0,
            0, 0, 0, 0, 349);
    }
}

// round 11
// speedup vs baseline: 1.3444x; 1.3444x over previous
#include <cuda_runtime.h>
#include <cuda_fp16.h>
#include <math.h>
#include <stdint.h>

// ---------------------------------------------------------------------------
// REGC hetero-GNN. Types [author 200000, fos 30000, inst 5000, paper 150000].
// 7 relations x 400000 edges. L1: 128->256 (H=8,NB=4,DH=32) mean+max.
// L2: 256->349 mean. fp16 HMMA GEMMs (register-prefetch mainloop, packed fp16
// weights); CSR aggregation, no feature atomics; fp16 intermediates.
// ---------------------------------------------------------------------------

#define E     400000
#define RTOT  885000
#define TOTE  2800000
#define NPAD  384

__device__ __half g_xh   [(size_t)385000 * 128];
__device__ __half g_bases[(size_t)385000 * 128];
__device__ __half g_out1 [(size_t)385000 * 256];   // post-ReLU
__device__ __half g_wroot[(size_t)385000 * 32];
__device__ __half g_wrel [(size_t)RTOT * 64];
__device__ __half g_sum2 [(size_t)RTOT * 256];
__device__ __half g_w1p  [4][(size_t)128 * NPAD];
__device__ float  g_b1p  [4][NPAD];
__device__ __half g_w2p  [4][(size_t)1024 * NPAD];
__device__ int    g_cnt   [RTOT];
__device__ int    g_rowptr[RTOT + 1];
__device__ int    g_cursor[RTOT];
__device__ int    g_ebuf  [TOTE];
__device__ int    g_bsum  [512];

__device__ __constant__ int c_ST[7]   = {0, 2, 0, 3, 3, 3, 1};
__device__ __constant__ int c_OFF[4]  = {0, 200000, 230000, 235000};
__device__ __constant__ int c_ROFF[7] = {0, 5000, 205000, 355000, 555000, 705000, 735000};

// ---------------------------------------------------------------------------
// fp16 GEMM, register-prefetch mainloop (R6-validated structure).
// A: up to 4 fp16 row-segments, aStride halves/row. B: packed [nit*32][NPAD].
// mode 0: C f32 = acc + bias (L2 logits, row stride 349, SCALAR stores --
//         349 odd => float2 would be misaligned on odd rows)
// mode 1: scatter cols [0,128)->g_bases, [128,160)->g_wroot, [160,..)->g_wrel
// ---------------------------------------------------------------------------
__global__ void __launch_bounds__(256) hgemm_h(
    const __half* A0, const __half* A1, const __half* A2, const __half* A3,
    const __half* __restrict__ Bp, const float* __restrict__ bias,
    float* __restrict__ Cf,
    int M, int aStride, int segShift, int nit, int mode,
    int nodeOff, int ro0, int ro1, int ro2, int Ncols)
{
    __shared__ __align__(16) __half As[128][40];
    __shared__ __align__(16) __half Bs[32][72];

    const __half* Aseg[4] = {A0, A1, A2, A3};
    const int tid  = threadIdx.x;
    const int lane = tid & 31;
    const int warp = tid >> 5;
    const int wm = (warp & 3) * 32;
    const int wn = (warp >> 2) * 32;
    const int m0 = blockIdx.y * 128;
    const int n0 = blockIdx.x * 64;

    // A: 128 rows x 32 halves; thread -> (row, 16-half chunk)
    const int am = tid >> 1;
    const int ak = (tid & 1) * 16;
    // B: 32 rows x 64 halves; thread -> (krow, 8-half chunk)
    const int bk = tid >> 3;
    const int bn = (tid & 7) * 8;

    uint4 pa0, pa1, pb;

    auto load_g = [&](int it) {
        const int seg = it >> segShift;
        const int k0 = (it - (seg << segShift)) * 32;
        const int gm = m0 + am;
        const __half* ap = Aseg[seg] + (size_t)(gm < M ? gm : 0) * aStride + k0 + ak;
        pa0 = *(const uint4*)ap;
        pa1 = *(const uint4*)(ap + 8);
        pb  = *(const uint4*)(Bp + (size_t)(it * 32 + bk) * NPAD + n0 + bn);
    };
    auto store_s = [&]() {
        *(uint4*)&As[am][ak]     = pa0;
        *(uint4*)&As[am][ak + 8] = pa1;
        *(uint4*)&Bs[bk][bn]     = pb;
    };

    float acc[2][4][4];
#pragma unroll
    for (int mi = 0; mi < 2; mi++)
#pragma unroll
        for (int nj = 0; nj < 4; nj++)
#pragma unroll
            for (int r = 0; r < 4; r++) acc[mi][nj][r] = 0.f;

    const uint32_t sA = (uint32_t)__cvta_generic_to_shared(&As[0][0]);
    const uint32_t sB = (uint32_t)__cvta_generic_to_shared(&Bs[0][0]);
    const uint32_t aAddr0 = sA + (uint32_t)((wm + (lane & 15)) * 80 + ((lane >> 4) * 8) * 2);
    const uint32_t bAddr0 = sB + (uint32_t)(((lane & 15)) * 144 + (wn + (lane >> 4) * 8) * 2);

    auto compute = [&]() {
#pragma unroll
        for (int kk = 0; kk < 2; kk++) {
            uint32_t a[2][4], b[4][2];
#pragma unroll
            for (int mi = 0; mi < 2; mi++) {
                uint32_t addr = aAddr0 + (uint32_t)(mi * 16 * 80 + kk * 16 * 2);
                asm volatile("ldmatrix.sync.aligned.m8n8.x4.shared.b16 {%0,%1,%2,%3}, [%4];"
                             : "=r"(a[mi][0]), "=r"(a[mi][1]), "=r"(a[mi][2]), "=r"(a[mi][3])
                             : "r"(addr));
            }
#pragma unroll
            for (int njp = 0; njp < 2; njp++) {
                uint32_t addr = bAddr0 + (uint32_t)(kk * 16 * 144 + njp * 16 * 2);
                asm volatile("ldmatrix.sync.aligned.m8n8.x4.trans.shared.b16 {%0,%1,%2,%3}, [%4];"
                             : "=r"(b[njp * 2][0]), "=r"(b[njp * 2][1]),
                               "=r"(b[njp * 2 + 1][0]), "=r"(b[njp * 2 + 1][1])
                             : "r"(addr));
            }
#pragma unroll
            for (int mi = 0; mi < 2; mi++)
#pragma unroll
                for (int nj = 0; nj < 4; nj++) {
                    asm volatile(
                        "mma.sync.aligned.m16n8k16.row.col.f32.f16.f16.f32 "
                        "{%0,%1,%2,%3}, {%4,%5,%6,%7}, {%8,%9}, {%0,%1,%2,%3};"
                        : "+f"(acc[mi][nj][0]), "+f"(acc[mi][nj][1]),
                          "+f"(acc[mi][nj][2]), "+f"(acc[mi][nj][3])
                        : "r"(a[mi][0]), "r"(a[mi][1]), "r"(a[mi][2]), "r"(a[mi][3]),
                          "r"(b[nj][0]), "r"(b[nj][1]));
                }
        }
    };

    load_g(0);
    store_s();
    __syncthreads();
    for (int it = 1; it < nit; it++) {
        load_g(it);
        compute();
        __syncthreads();
        store_s();
        __syncthreads();
    }
    compute();

    // ---- epilogue ----
#pragma unroll
    for (int mi = 0; mi < 2; mi++)
#pragma unroll
        for (int nj = 0; nj < 4; nj++)
#pragma unroll
            for (int rp = 0; rp < 2; rp++) {
                const int row = m0 + wm + mi * 16 + (lane >> 2) + rp * 8;
                const int col = n0 + wn + nj * 8 + (lane & 3) * 2;
                if (row >= M || col >= Ncols) continue;
                const bool pair = (col + 1 < Ncols);
                const float v0 = acc[mi][nj][rp * 2 + 0] + bias[col];
                const float v1 = acc[mi][nj][rp * 2 + 1] + bias[pair ? col + 1 : col];
                if (mode == 0) {
                    // 349-stride rows: only 4B alignment guaranteed -> scalar
                    float* p = Cf + (size_t)row * 349 + col;
                    p[0] = v0;
                    if (pair) p[1] = v1;
                } else {
                    const __half2 h2 = __floats2half2_rn(v0, v1);
                    if (col < 128) {
                        *(__half2*)(g_bases + (size_t)(nodeOff + row) * 128 + col) = h2;
                    } else if (col < 160) {
                        *(__half2*)(g_wroot + (size_t)(nodeOff + row) * 32 + (col - 128)) = h2;
                    } else {
                        const int cc = col - 160;
                        const int rr = cc >> 6;
                        const int ro = (rr == 0) ? ro0 : ((rr == 1) ? ro1 : ro2);
                        *(__half2*)(g_wrel + (size_t)(ro + row) * 64 + (cc & 63)) = h2;
                    }
                }
            }
}

// ---------------------------------------------------------------------------
// prep kernels (validated R8)
// ---------------------------------------------------------------------------
__global__ void cvt_half(const float* __restrict__ x, __half* __restrict__ y, int n)
{
    const int i = blockIdx.x * blockDim.x + threadIdx.x;
    if (i < n) y[i] = __float2half_rn(x[i]);
}

__global__ void pack_w1(const float* __restrict__ bases_w1,
                        const float* __restrict__ root_w1,
                        const float* __restrict__ rel_w1,
                        const float* __restrict__ root_b1,
                        const float* __restrict__ rel_b1,
                        __half* __restrict__ w1p, float* __restrict__ b1p,
                        int t, int R, int e0, int e1, int e2)
{
    const int i = blockIdx.x * blockDim.x + threadIdx.x;
    if (i >= 128 * NPAD) return;
    const int k = i / NPAD, n = i % NPAD;
    float v = 0.f, b = 0.f;
    if (n < 128) {
        v = bases_w1[k * 128 + n];
    } else if (n < 160) {
        v = root_w1[((size_t)t * 32 + (n - 128)) * 128 + k];
        b = root_b1[t * 32 + (n - 128)];
    } else {
        const int cc = n - 160;
        const int r = cc >> 6;
        if (r < R) {
            const int e = (r == 0) ? e0 : ((r == 1) ? e1 : e2);
            v = rel_w1[((size_t)e * 64 + (cc & 63)) * 128 + k];
            b = rel_b1[e * 64 + (cc & 63)];
        }
    }
    w1p[(size_t)k * NPAD + n] = __float2half_rn(v);
    if (k == 0) b1p[n] = b;
}

__global__ void pack_w2(const float* __restrict__ root_w2,
                        const float* __restrict__ rel_w2,
                        __half* __restrict__ w2p,
                        int t, int nseg, int e1, int e2, int e3)
{
    const int i = blockIdx.x * blockDim.x + threadIdx.x;
    if (i >= nseg * 256 * NPAD) return;
    const int kg = i / NPAD, n = i % NPAD;
    const int seg = kg >> 8, k = kg & 255;
    float v = 0.f;
    if (n < 349) {
        if (seg == 0) v = root_w2[((size_t)t * 349 + n) * 256 + k];
        else {
            const int e = (seg == 1) ? e1 : ((seg == 2) ? e2 : e3);
            v = rel_w2[((size_t)e * 349 + n) * 256 + k];
        }
    }
    w2p[(size_t)kg * NPAD + n] = __float2half_rn(v);
}

// ---------------------------------------------------------------------------
// CSR build (validated R5-R8)
// ---------------------------------------------------------------------------
__global__ void count_kernel(const int* __restrict__ dst_idx)
{
    const int e = blockIdx.y;
    const int i = blockIdx.x * blockDim.x + threadIdx.x;
    if (i >= E) return;
    atomicAdd(&g_cnt[c_ROFF[e] + dst_idx[(size_t)e * E + i]], 1);
}

__global__ void __launch_bounds__(256) scan1_kernel()
{
    __shared__ int s[256];
    const int tid = threadIdx.x;
    const int tbase = blockIdx.x * 2048 + tid * 8;
    int vals[8];
    int tsum = 0;
#pragma unroll
    for (int j = 0; j < 8; j++) {
        int v = (tbase + j < RTOT) ? g_cnt[tbase + j] : 0;
        vals[j] = tsum;
        tsum += v;
    }
    s[tid] = tsum;
    __syncthreads();
    for (int off = 1; off < 256; off <<= 1) {
        int t = (tid >= off) ? s[tid - off] : 0;
        __syncthreads();
        s[tid] += t;
        __syncthreads();
    }
    const int texcl = (tid > 0) ? s[tid - 1] : 0;
    if (tid == 255) g_bsum[blockIdx.x] = s[255];
#pragma unroll
    for (int j = 0; j < 8; j++)
        if (tbase + j < RTOT) g_rowptr[tbase + j] = vals[j] + texcl;
}

__global__ void __launch_bounds__(512) scan2_kernel(int nb)
{
    __shared__ int s[512];
    const int tid = threadIdx.x;
    s[tid] = (tid < nb) ? g_bsum[tid] : 0;
    __syncthreads();
    for (int off = 1; off < 512; off <<= 1) {
        int t = (tid >= off) ? s[tid - off] : 0;
        __syncthreads();
        s[tid] += t;
        __syncthreads();
    }
    g_bsum[tid] = (tid > 0) ? s[tid - 1] : 0;
}

__global__ void scan3_kernel()
{
    const int i = blockIdx.x * blockDim.x + threadIdx.x;
    if (i < RTOT) {
        int v = g_rowptr[i] + g_bsum[i >> 11];
        g_rowptr[i] = v;
        g_cursor[i] = v;
    } else if (i == RTOT) {
        g_rowptr[RTOT] = TOTE;
    }
}

__global__ void fill_kernel(const int* __restrict__ src_idx,
                            const int* __restrict__ dst_idx)
{
    const int e = blockIdx.y;
    const int i = blockIdx.x * blockDim.x + threadIdx.x;
    if (i >= E) return;
    const int d = dst_idx[(size_t)e * E + i];
    const int s = src_idx[(size_t)e * E + i];
    const int pos = atomicAdd(&g_cursor[c_ROFF[e] + d], 1);
    g_ebuf[pos] = c_OFF[c_ST[e]] + s;
}

// ---------------------------------------------------------------------------
// L1 fused aggregate+combine (R6-validated; + index prefetch)
// ---------------------------------------------------------------------------
__global__ void __launch_bounds__(256) l1_fused_kernel(
    __half* __restrict__ out1, const __half* __restrict__ wroot,
    int tOff, int Nn, int roff0, int roff1, int roff2, int R)
{
    __shared__ float smb[8][128];
    __shared__ float sma[8][256];

    const int warp = threadIdx.x >> 5;
    const int lane = threadIdx.x & 31;
    const int n = blockIdx.x * 8 + warp;
    if (n >= Nn) return;
    const int c4 = lane * 4;
    const int h  = lane >> 2;

    {
        const uint2 raw = *(const uint2*)(g_bases + (size_t)(tOff + n) * 128 + c4);
        const float2 lo = __half22float2(*(const __half2*)&raw.x);
        const float2 hi = __half22float2(*(const __half2*)&raw.y);
        smb[warp][c4 + 0] = lo.x; smb[warp][c4 + 1] = lo.y;
        smb[warp][c4 + 2] = hi.x; smb[warp][c4 + 3] = hi.y;
    }
    __syncwarp();

    float val[8];
    {
        const uint2 raw = *(const uint2*)(wroot + (size_t)n * 32 + h * 4);
        const float2 w01 = __half22float2(*(const __half2*)&raw.x);
        const float2 w23 = __half22float2(*(const __half2*)&raw.y);
#pragma unroll
        for (int j = 0; j < 8; j++) {
            const int dd = (lane * 8 + j) & 31;
            val[j] = w01.x * smb[warp][dd] + w01.y * smb[warp][32 + dd] +
                     w23.x * smb[warp][64 + dd] + w23.y * smb[warp][96 + dd];
        }
    }

    const int roffs[3] = {roff0, roff1, roff2};
    for (int r = 0; r < R; r++) {
        const int g = roffs[r] + n;
        const int rs = g_rowptr[g];
        const int re = g_rowptr[g + 1];
        const int ct = re - rs;
        float4 s4 = make_float4(0.f, 0.f, 0.f, 0.f);
        float4 m4 = make_float4(-INFINITY, -INFINITY, -INFINITY, -INFINITY);
        int idx = (rs < re) ? g_ebuf[rs] : 0;
        for (int k = rs; k < re; k++) {
            const int nidx = (k + 1 < re) ? g_ebuf[k + 1] : 0;
            const uint2 raw = *(const uint2*)(g_bases + (size_t)idx * 128 + c4);
            const float2 lo = __half22float2(*(const __half2*)&raw.x);
            const float2 hi = __half22float2(*(const __half2*)&raw.y);
            s4.x += lo.x; s4.y += lo.y; s4.z += hi.x; s4.w += hi.y;
            m4.x = fmaxf(m4.x, lo.x); m4.y = fmaxf(m4.y, lo.y);
            m4.z = fmaxf(m4.z, hi.x); m4.w = fmaxf(m4.w, hi.y);
            idx = nidx;
        }
        const float inv = 1.f / (float)(ct > 1 ? ct : 1);
        s4.x *= inv; s4.y *= inv; s4.z *= inv; s4.w *= inv;
        if (ct == 0) m4 = make_float4(0.f, 0.f, 0.f, 0.f);
        *(float4*)&sma[warp][c4]       = s4;
        *(float4*)&sma[warp][128 + c4] = m4;
        __syncwarp();
        const uint4 raw = *(const uint4*)(g_wrel + (size_t)g * 64 + h * 8);
        const float2 w01 = __half22float2(*(const __half2*)&raw.x);
        const float2 w23 = __half22float2(*(const __half2*)&raw.y);
        const float2 w45 = __half22float2(*(const __half2*)&raw.z);
        const float2 w67 = __half22float2(*(const __half2*)&raw.w);
        const float wv[8] = {w01.x, w01.y, w23.x, w23.y, w45.x, w45.y, w67.x, w67.y};
#pragma unroll
        for (int j = 0; j < 8; j++) {
            const int dd = (lane * 8 + j) & 31;
#pragma unroll
            for (int b = 0; b < 8; b++)
                val[j] += wv[b] * sma[warp][b * 32 + dd];
        }
        __syncwarp();
    }

    union { __half2 h[4]; uint4 u; } pk;
#pragma unroll
    for (int q = 0; q < 4; q++)
        pk.h[q] = __floats2half2_rn(fmaxf(val[2 * q], 0.f), fmaxf(val[2 * q + 1], 0.f));
    *(uint4*)(out1 + (size_t)n * 256 + lane * 8) = pk.u;
}

// ---------------------------------------------------------------------------
// L2 aggregation (R6-validated; + index prefetch)
// ---------------------------------------------------------------------------
__global__ void __launch_bounds__(256) l2_agg_kernel()
{
    const int warp = threadIdx.x >> 5;
    const int lane = threadIdx.x & 31;
    const int g = blockIdx.x * 8 + warp;
    if (g >= RTOT) return;
    const int c8 = lane * 8;
    const int rs = g_rowptr[g];
    const int re = g_rowptr[g + 1];
    const int ct = re - rs;
    float a[8];
#pragma unroll
    for (int j = 0; j < 8; j++) a[j] = 0.f;
    int idx = (rs < re) ? g_ebuf[rs] : 0;
    for (int k = rs; k < re; k++) {
        const int nidx = (k + 1 < re) ? g_ebuf[k + 1] : 0;
        const uint4 raw = *(const uint4*)(g_out1 + (size_t)idx * 256 + c8);
        const float2 v0 = __half22float2(*(const __half2*)&raw.x);
        const float2 v1 = __half22float2(*(const __half2*)&raw.y);
        const float2 v2 = __half22float2(*(const __half2*)&raw.z);
        const float2 v3 = __half22float2(*(const __half2*)&raw.w);
        a[0] += v0.x; a[1] += v0.y; a[2] += v1.x; a[3] += v1.y;
        a[4] += v2.x; a[5] += v2.y; a[6] += v3.x; a[7] += v3.y;
        idx = nidx;
    }
    const float inv = 1.f / (float)(ct > 1 ? ct : 1);
    union { __half2 h[4]; uint4 u; } pk;
#pragma unroll
    for (int q = 0; q < 4; q++)
        pk.h[q] = __floats2half2_rn(a[2 * q] * inv, a[2 * q + 1] * inv);
    *(uint4*)(g_sum2 + (size_t)g * 256 + c8) = pk.u;
}

// ---------------------------------------------------------------------------
// host
// ---------------------------------------------------------------------------
extern "C" void kernel_launch(void* const* d_in, const int* in_sizes, int n_in,
                              void* d_out, int out_size)
{
    const float* x_paper    = (const float*)d_in[0];
    const float* emb_author = (const float*)d_in[1];
    const float* emb_fos    = (const float*)d_in[2];
    const float* emb_inst   = (const float*)d_in[3];
    const float* bases_w1   = (const float*)d_in[4];
    const float* rel_w1     = (const float*)d_in[5];
    const float* rel_b1     = (const float*)d_in[6];
    const float* root_w1    = (const float*)d_in[7];
    const float* root_b1    = (const float*)d_in[8];
    const float* rel_w2     = (const float*)d_in[9];
    const float* root_w2    = (const float*)d_in[10];
    const float* root_b2    = (const float*)d_in[11];
    const int*   src_idx    = (const int*)d_in[12];
    const int*   dst_idx    = (const int*)d_in[13];
    float* out = (float*)d_out;

    static const int NUMSh[4] = {200000, 30000, 5000, 150000};
    static const int OFFh[4]  = {0, 200000, 230000, 235000};
    static const int DT[7] = {2, 0, 3, 0, 3, 1, 3};
    static const int ROFFh[7] = {0, 5000, 205000, 355000, 555000, 705000, 735000};

    __half *xh_p, *bases_p, *out1_p, *wroot_p, *wrel_p, *sum2_p, *w1p_p, *w2p_p;
    float* b1p_p;
    int* cnt_p;
    cudaGetSymbolAddress((void**)&xh_p,    g_xh);
    cudaGetSymbolAddress((void**)&bases_p, g_bases);
    cudaGetSymbolAddress((void**)&out1_p,  g_out1);
    cudaGetSymbolAddress((void**)&wroot_p, g_wroot);
    cudaGetSymbolAddress((void**)&wrel_p,  g_wrel);
    cudaGetSymbolAddress((void**)&sum2_p,  g_sum2);
    cudaGetSymbolAddress((void**)&w1p_p,   g_w1p);
    cudaGetSymbolAddress((void**)&b1p_p,   g_b1p);
    cudaGetSymbolAddress((void**)&w2p_p,   g_w2p);
    cudaGetSymbolAddress((void**)&cnt_p,   g_cnt);

    const float* xs[4] = {emb_author, emb_fos, emb_inst, x_paper};

    // ---- CSR build ----
    cudaMemsetAsync(cnt_p, 0, (size_t)RTOT * sizeof(int));
    {
        dim3 grid((E + 255) / 256, 7);
        count_kernel<<<grid, 256>>>(dst_idx);
    }
    scan1_kernel<<<(RTOT + 2047) / 2048, 256>>>();
    scan2_kernel<<<1, 512>>>((RTOT + 2047) / 2048);
    scan3_kernel<<<(RTOT + 1 + 255) / 256, 256>>>();
    {
        dim3 grid((E + 255) / 256, 7);
        fill_kernel<<<grid, 256>>>(src_idx, dst_idx);
    }

    // ---- prep ----
    for (int t = 0; t < 4; t++) {
        const int n = NUMSh[t] * 128;
        cvt_half<<<(n + 255) / 256, 256>>>(xs[t], xh_p + (size_t)OFFh[t] * 128, n);
    }
    int relsOf[4][3], Rof[4];
    for (int t = 0; t < 4; t++) {
        Rof[t] = 0;
        for (int e = 0; e < 7; e++)
            if (DT[e] == t) relsOf[t][Rof[t]++] = e;
        for (int r = Rof[t]; r < 3; r++) relsOf[t][r] = relsOf[t][0];
    }
    for (int t = 0; t < 4; t++) {
        pack_w1<<<(128 * NPAD + 255) / 256, 256>>>(
            bases_w1, root_w1, rel_w1, root_b1, rel_b1,
            w1p_p + (size_t)t * 128 * NPAD, b1p_p + (size_t)t * NPAD,
            t, Rof[t], relsOf[t][0], relsOf[t][1], relsOf[t][2]);
        const int nseg = 1 + Rof[t];
        pack_w2<<<(nseg * 256 * NPAD + 255) / 256, 256>>>(
            root_w2, rel_w2, w2p_p + (size_t)t * 1024 * NPAD,
            t, nseg, relsOf[t][0], relsOf[t][1], relsOf[t][2]);
    }

    // ---- layer-1 merged GEMM per type ----
    for (int t = 0; t < 4; t++) {
        const int Ncols = 160 + 64 * Rof[t];
        const __half* A = xh_p + (size_t)OFFh[t] * 128;
        dim3 grid((Ncols + 63) / 64, (NUMSh[t] + 127) / 128);
        hgemm_h<<<grid, 256>>>(
            A, A, A, A, w1p_p + (size_t)t * 128 * NPAD, b1p_p + (size_t)t * NPAD,
            out, NUMSh[t], 128, 16, 4, 1,
            OFFh[t], ROFFh[relsOf[t][0]], ROFFh[relsOf[t][1]], ROFFh[relsOf[t][2]],
            Ncols);
    }

    // ---- layer-1 fused aggregate+combine ----
    for (int t = 0; t < 4; t++) {
        l1_fused_kernel<<<(NUMSh[t] + 7) / 8, 256>>>(
            out1_p + (size_t)OFFh[t] * 256, wroot_p + (size_t)OFFh[t] * 32,
            OFFh[t], NUMSh[t],
            ROFFh[relsOf[t][0]], ROFFh[relsOf[t][1]], ROFFh[relsOf[t][2]], Rof[t]);
    }

    // ---- layer-2 aggregation ----
    l2_agg_kernel<<<(RTOT + 7) / 8, 256>>>();

    // ---- layer-2 multi-segment GEMM per type ----
    for (int t = 0; t < 4; t++) {
        const __half* A[4];
        A[0] = out1_p + (size_t)OFFh[t] * 256;
        int nseg = 1;
        for (int r = 0; r < Rof[t]; r++)
            A[nseg++] = sum2_p + (size_t)ROFFh[relsOf[t][r]] * 256;
        for (int s2 = nseg; s2 < 4; s2++) A[s2] = A[0];
        dim3 grid(6, (NUMSh[t] + 127) / 128);
        hgemm_h<<<grid, 256>>>(
            A[0], A[1], A[2], A[3], w2p_p + (size_t)t * 1024 * NPAD,
            root_b2 + (size_t)t * 349,
            out + (size_t)OFFh[t] * 349, NUMSh[t], 256, 3, nseg * 8, 0,
            0, 0, 0, 0, 349);
    }
}